// round 7
// baseline (speedup 1.0000x reference)
#include <cuda_runtime.h>
#include <mma.h>
#include <cstdint>

using namespace nvcuda;

constexpr int INC  = 768;
constexpr int CAv  = 384;
constexpr int BTv  = 128;
constexpr int Tv   = 16;
constexpr int Hv   = 14;
constexpr int Wv   = 14;
constexpr int Lv   = 197;
constexpr int NP   = 196;
constexpr int MTOT = BTv * NP;       // 25088
constexpr int TILE3D = Tv * NP;      // 3136

__device__ float g_h0[CAv * MTOT];   // channel-outer: [ca][m]
__device__ float g_h2[CAv * MTOT];

#define BK 16
#define PAD    20    // k-tile row stride
#define PAD_AT 132   // fc2 transposed-A row stride
#define PCM    260   // fc1 C staging col-major ldm (mult of 4)
#define PCR    68    // fc2 C staging row-major ldm (mult of 4)

// fc1: BM=256, BN=128; warps 4x2, each 64x64
constexpr int BM1 = 256, BN1 = 128;
constexpr int A1SZ = BM1 * PAD;          // 5120
constexpr int B1SZ = BN1 * PAD;          // 2560
constexpr int BUF1 = A1SZ + B1SZ;        // 7680
constexpr int FC1_BYTES = 2 * BUF1 * 4;  // 61440

// fc2: BM=128, BN=256; warps 2x4, each 64x64
constexpr int BM2 = 128, BN2 = 256;
constexpr int A2SZ = BK * PAD_AT;        // 2112
constexpr int B2SZ = BN2 * PAD;          // 5120
constexpr int BUF2 = A2SZ + B2SZ;        // 7232
constexpr int FC2_BYTES = 2 * BUF2 * 4;  // 57856

// ---------------------------------------------------------------------------
__device__ __forceinline__ void cp_async16(float* smem_dst, const float* gmem_src) {
    uint32_t s = (uint32_t)__cvta_generic_to_shared(smem_dst);
    asm volatile("cp.async.cg.shared.global [%0], [%1], 16;\n" :: "r"(s), "l"(gmem_src));
}
__device__ __forceinline__ void cp_commit() { asm volatile("cp.async.commit_group;\n"); }
__device__ __forceinline__ void cp_wait_all() { asm volatile("cp.async.wait_group 0;\n"); }

// ---------------------------------------------------------------------------
// fc1: h0[n, m] = sum_k x[m,k] * w[n,k] + bias[n]   (output TRANSPOSED)
// ---------------------------------------------------------------------------
__global__ __launch_bounds__(256, 1) void fc1_kernel(
    const float* __restrict__ x,
    const float* __restrict__ w,
    const float* __restrict__ bias)
{
    extern __shared__ __align__(16) float smem[];

    const int m0  = blockIdx.y * BM1;
    const int n0  = blockIdx.x * BN1;
    const int tid = threadIdx.x;
    const int wid = tid >> 5;
    const int wm  = wid & 3;     // 4 warps along M (64 each)
    const int wn  = wid >> 2;    // 2 warps along N (64 each)

    wmma::fragment<wmma::accumulator, 16, 16, 8, float> acc[4][4];
    #pragma unroll
    for (int i = 0; i < 4; i++)
        #pragma unroll
        for (int j = 0; j < 4; j++)
            wmma::fill_fragment(acc[i][j], 0.0f);

    // Loaders: idx = tid + u*256; r = idx>>2, c4 = (idx&3)*4
    size_t abase[4]; size_t bbase[2];
    int lr[4], lc[4];
    #pragma unroll
    for (int u = 0; u < 4; u++) {
        int idx = tid + u * 256;
        lr[u] = idx >> 2;
        lc[u] = (idx & 3) * 4;
        int m  = m0 + lr[u];
        int bt = m / NP;
        int pos = m - bt * NP;
        abase[u] = ((size_t)(bt * Lv + 1 + pos)) * INC;
    }
    #pragma unroll
    for (int u = 0; u < 2; u++) {
        int idx = tid + u * 256;
        bbase[u] = (size_t)(n0 + (idx >> 2)) * INC;
    }

    constexpr int KT = INC / BK;   // 48

    // Prefetch tile 0
    {
        float* As = smem; float* Bs = smem + A1SZ;
        #pragma unroll
        for (int u = 0; u < 4; u++)
            cp_async16(&As[lr[u] * PAD + lc[u]], &x[abase[u] + lc[u]]);
        #pragma unroll
        for (int u = 0; u < 2; u++) {
            int idx = tid + u * 256;
            cp_async16(&Bs[(idx >> 2) * PAD + (idx & 3) * 4], &w[bbase[u] + (idx & 3) * 4]);
        }
        cp_commit();
    }

    for (int kt = 0; kt < KT; kt++) {
        cp_wait_all();
        __syncthreads();

        if (kt + 1 < KT) {
            int k0n = (kt + 1) * BK;
            float* As = smem + ((kt + 1) & 1) * BUF1;
            float* Bs = As + A1SZ;
            #pragma unroll
            for (int u = 0; u < 4; u++)
                cp_async16(&As[lr[u] * PAD + lc[u]], &x[abase[u] + k0n + lc[u]]);
            #pragma unroll
            for (int u = 0; u < 2; u++) {
                int idx = tid + u * 256;
                cp_async16(&Bs[(idx >> 2) * PAD + (idx & 3) * 4], &w[bbase[u] + k0n + (idx & 3) * 4]);
            }
            cp_commit();
        }

        float* As = smem + (kt & 1) * BUF1;
        float* Bs = As + A1SZ;
        #pragma unroll
        for (int kk = 0; kk < BK; kk += 8) {
            wmma::fragment<wmma::matrix_a, 16, 16, 8, wmma::precision::tf32, wmma::row_major> af[4];
            wmma::fragment<wmma::matrix_b, 16, 16, 8, wmma::precision::tf32, wmma::col_major> bf[4];
            #pragma unroll
            for (int i = 0; i < 4; i++)
                wmma::load_matrix_sync(af[i], &As[(wm * 64 + i * 16) * PAD + kk], PAD);
            #pragma unroll
            for (int j = 0; j < 4; j++)
                wmma::load_matrix_sync(bf[j], &Bs[(wn * 64 + j * 16) * PAD + kk], PAD);
            #pragma unroll
            for (int i = 0; i < 4; i++)
                #pragma unroll
                for (int j = 0; j < 4; j++)
                    wmma::mma_sync(acc[i][j], af[i], bf[j], acc[i][j]);
        }
    }
    __syncthreads();

    // Epilogue: 4 passes of 32 cols, staged COL-MAJOR (ldm=260)
    #pragma unroll
    for (int pass = 0; pass < 4; pass++) {
        if (wn == (pass >> 1)) {
            int jb = (pass & 1) * 2;
            #pragma unroll
            for (int i = 0; i < 4; i++)
                #pragma unroll
                for (int j2 = 0; j2 < 2; j2++)
                    wmma::store_matrix_sync(&smem[(j2 * 16) * PCM + wm * 64 + i * 16],
                                            acc[i][jb + j2], PCM, wmma::mem_col_major);
        }
        __syncthreads();
        #pragma unroll
        for (int it = 0; it < 32; it++) {
            int e = tid + it * 256;
            int col = e >> 8, r = e & 255;
            int n = n0 + pass * 32 + col;
            g_h0[(size_t)n * MTOT + m0 + r] = smem[col * PCM + r] + bias[n];
        }
        __syncthreads();
    }
}

// ---------------------------------------------------------------------------
// Fused convs (unchanged structurally)
// ---------------------------------------------------------------------------
__global__ __launch_bounds__(256) void conv_fused_kernel(
    const float* __restrict__ w1, const float* __restrict__ b1,
    const float* __restrict__ w2, const float* __restrict__ b2,
    const float* __restrict__ w3, const float* __restrict__ b3,
    const float* __restrict__ wp, const float* __restrict__ pb)
{
    __shared__ float s0[TILE3D];
    __shared__ float s1[TILE3D];

    const int tid = threadIdx.x;
    const int ca  = blockIdx.x % CAv;
    const int b   = blockIdx.x / CAv;
    const size_t base = (size_t)ca * MTOT + (size_t)b * TILE3D;

    for (int i = tid * 4; i < TILE3D; i += 1024)
        *reinterpret_cast<float4*>(&s0[i]) =
            *reinterpret_cast<const float4*>(&g_h0[base + i]);

    float wc[27];
    #pragma unroll
    for (int j = 0; j < 27; j++) wc[j] = w3[ca * 27 + j];
    #pragma unroll
    for (int j = 0; j < 9; j++)  wc[9 + j] += w2[ca * 9 + j];
    #pragma unroll
    for (int dt = 0; dt < 3; dt++) wc[dt * 9 + 4] += w1[ca * 3 + dt];
    const float bias3 = (b1[ca] + b2[ca] + b3[ca]) * (1.0f / 3.0f);
    const float wp0 = wp[ca * 3], wp1 = wp[ca * 3 + 1], wp2 = wp[ca * 3 + 2];
    const float pbias = pb[ca];

    __syncthreads();

    for (int e = tid; e < TILE3D; e += 256) {
        int t   = e / NP;
        int pos = e - t * NP;
        int y   = pos / Wv;
        int x   = pos - y * Wv;
        float acc = 0.0f;
        #pragma unroll
        for (int dt = -1; dt <= 1; dt++) {
            int tt = t + dt;
            if ((unsigned)tt >= (unsigned)Tv) continue;
            #pragma unroll
            for (int dy = -1; dy <= 1; dy++) {
                int yy = y + dy;
                if ((unsigned)yy >= (unsigned)Hv) continue;
                #pragma unroll
                for (int dx = -1; dx <= 1; dx++) {
                    int xx = x + dx;
                    if ((unsigned)xx >= (unsigned)Wv) continue;
                    acc += wc[(dt + 1) * 9 + (dy + 1) * 3 + (dx + 1)]
                           * s0[tt * NP + yy * Wv + xx];
                }
            }
        }
        s1[e] = acc * (1.0f / 3.0f) + bias3 + s0[e];
    }
    __syncthreads();

    for (int e = tid; e < TILE3D; e += 256) {
        int t = e / NP;
        float acc = pbias;
        if (t > 0)      acc += wp0 * s1[e - NP];
        acc += wp1 * s1[e];
        if (t < Tv - 1) acc += wp2 * s1[e + NP];
        g_h2[base + e] = s1[e] + acc;
    }
}

// ---------------------------------------------------------------------------
// fc2: out[m, n] = x[m, n] + sum_k h2[k, m] * w[n, k] + bias[n]
// ---------------------------------------------------------------------------
__global__ __launch_bounds__(256, 1) void fc2_kernel(
    const float* __restrict__ w,
    const float* __restrict__ bias,
    const float* __restrict__ x,
    float* __restrict__ out)
{
    extern __shared__ __align__(16) float smem[];

    const int m0  = blockIdx.y * BM2;
    const int n0  = blockIdx.x * BN2;
    const int tid = threadIdx.x;
    const int wid = tid >> 5;
    const int wm  = wid & 1;     // 2 warps along M (64 each)
    const int wn  = wid >> 1;    // 4 warps along N (64 each)

    wmma::fragment<wmma::accumulator, 16, 16, 8, float> acc[4][4];
    #pragma unroll
    for (int i = 0; i < 4; i++)
        #pragma unroll
        for (int j = 0; j < 4; j++)
            wmma::fill_fragment(acc[i][j], 0.0f);

    // A loader: u<2: kr = idx>>5 (0..15), mc = (idx&31)*4
    // B loader: u<4: r = idx>>2 (0..255), c4 = (idx&3)*4
    int akr[2], amc[2];
    size_t bbase[4]; int bc[4];
    #pragma unroll
    for (int u = 0; u < 2; u++) {
        int idx = tid + u * 256;
        akr[u] = idx >> 5;
        amc[u] = (idx & 31) * 4;
    }
    #pragma unroll
    for (int u = 0; u < 4; u++) {
        int idx = tid + u * 256;
        bbase[u] = (size_t)(n0 + (idx >> 2)) * CAv;
        bc[u] = (idx & 3) * 4;
    }

    constexpr int KT = CAv / BK;   // 24

    {
        float* As = smem; float* Bs = smem + A2SZ;
        #pragma unroll
        for (int u = 0; u < 2; u++)
            cp_async16(&As[akr[u] * PAD_AT + amc[u]],
                       &g_h2[(size_t)akr[u] * MTOT + m0 + amc[u]]);
        #pragma unroll
        for (int u = 0; u < 4; u++) {
            int idx = tid + u * 256;
            cp_async16(&Bs[(idx >> 2) * PAD + bc[u]], &w[bbase[u] + bc[u]]);
        }
        cp_commit();
    }

    for (int kt = 0; kt < KT; kt++) {
        cp_wait_all();
        __syncthreads();

        if (kt + 1 < KT) {
            int k0n = (kt + 1) * BK;
            float* As = smem + ((kt + 1) & 1) * BUF2;
            float* Bs = As + A2SZ;
            #pragma unroll
            for (int u = 0; u < 2; u++)
                cp_async16(&As[akr[u] * PAD_AT + amc[u]],
                           &g_h2[(size_t)(k0n + akr[u]) * MTOT + m0 + amc[u]]);
            #pragma unroll
            for (int u = 0; u < 4; u++) {
                int idx = tid + u * 256;
                cp_async16(&Bs[(idx >> 2) * PAD + bc[u]], &w[bbase[u] + k0n + bc[u]]);
            }
            cp_commit();
        }

        float* As = smem + (kt & 1) * BUF2;
        float* Bs = As + A2SZ;
        #pragma unroll
        for (int kk = 0; kk < BK; kk += 8) {
            wmma::fragment<wmma::matrix_a, 16, 16, 8, wmma::precision::tf32, wmma::col_major> af[4];
            wmma::fragment<wmma::matrix_b, 16, 16, 8, wmma::precision::tf32, wmma::col_major> bf[4];
            #pragma unroll
            for (int i = 0; i < 4; i++)
                wmma::load_matrix_sync(af[i], &As[kk * PAD_AT + wm * 64 + i * 16], PAD_AT);
            #pragma unroll
            for (int j = 0; j < 4; j++)
                wmma::load_matrix_sync(bf[j], &Bs[(wn * 64 + j * 16) * PAD + kk], PAD);
            #pragma unroll
            for (int i = 0; i < 4; i++)
                #pragma unroll
                for (int j = 0; j < 4; j++)
                    wmma::mma_sync(acc[i][j], af[i], bf[j], acc[i][j]);
        }
    }
    __syncthreads();

    // Epilogue: 4 passes of 64 cols, ROW-MAJOR staging (ldm=68)
    #pragma unroll
    for (int pass = 0; pass < 4; pass++) {
        if (wn == pass) {
            #pragma unroll
            for (int i = 0; i < 4; i++)
                #pragma unroll
                for (int j = 0; j < 4; j++)
                    wmma::store_matrix_sync(&smem[(wm * 64 + i * 16) * PCR + j * 16],
                                            acc[i][j], PCR, wmma::mem_row_major);
        }
        __syncthreads();
        #pragma unroll
        for (int it = 0; it < 32; it++) {
            int e = tid + it * 256;
            int c = e & 63, r = e >> 6;
            int m = m0 + r;
            int bt = m / NP;
            int pos = m - bt * NP;
            int n = n0 + pass * 64 + c;
            size_t off = ((size_t)(bt * Lv + 1 + pos)) * INC + n;
            out[off] = x[off] + smem[r * PCR + c] + bias[n];
        }
        __syncthreads();
    }
}

// ---------------------------------------------------------------------------
__global__ __launch_bounds__(256) void cls_kernel(
    const float* __restrict__ x, float* __restrict__ out)
{
    int i = blockIdx.x * 256 + threadIdx.x;
    if (i >= BTv * INC) return;
    int bt = i / INC, c = i % INC;
    size_t off = (size_t)bt * Lv * INC + c;
    out[off] = x[off];
}

// ---------------------------------------------------------------------------
extern "C" void kernel_launch(void* const* d_in, const int* in_sizes, int n_in,
                              void* d_out, int out_size)
{
    const float* x     = (const float*)d_in[0];
    const float* fc1_w = (const float*)d_in[1];
    const float* fc1_b = (const float*)d_in[2];
    const float* c1w   = (const float*)d_in[3];
    const float* c1b   = (const float*)d_in[4];
    const float* c2w   = (const float*)d_in[5];
    const float* c2b   = (const float*)d_in[6];
    const float* c3w   = (const float*)d_in[7];
    const float* c3b   = (const float*)d_in[8];
    const float* pw    = (const float*)d_in[9];
    const float* pb    = (const float*)d_in[10];
    const float* fc2_w = (const float*)d_in[11];
    const float* fc2_b = (const float*)d_in[12];
    float* out = (float*)d_out;

    cudaFuncSetAttribute(fc1_kernel, cudaFuncAttributeMaxDynamicSharedMemorySize, FC1_BYTES);
    cudaFuncSetAttribute(fc2_kernel, cudaFuncAttributeMaxDynamicSharedMemorySize, FC2_BYTES);

    dim3 g1(CAv / BN1, MTOT / BM1);   // (3, 98)
    fc1_kernel<<<g1, 256, FC1_BYTES>>>(x, fc1_w, fc1_b);

    conv_fused_kernel<<<CAv * (BTv / Tv), 256>>>(c1w, c1b, c2w, c2b, c3w, c3b, pw, pb);

    dim3 g2(INC / BN2, MTOT / BM2);   // (3, 196)
    fc2_kernel<<<g2, 256, FC2_BYTES>>>(fc2_w, fc2_b, x, out);

    cls_kernel<<<(BTv * INC + 255) / 256, 256>>>(x, out);
}

// round 9
// speedup vs baseline: 2.0218x; 2.0218x over previous
#include <cuda_runtime.h>
#include <cuda_fp16.h>
#include <mma.h>
#include <cstdint>

using namespace nvcuda;

constexpr int INC  = 768;
constexpr int CAv  = 384;
constexpr int BTv  = 128;
constexpr int Tv   = 16;
constexpr int Hv   = 14;
constexpr int Wv   = 14;
constexpr int Lv   = 197;
constexpr int NP   = 196;
constexpr int MTOT = BTv * NP;       // 25088
constexpr int TILE3D = Tv * NP;      // 3136

// Scratch (device globals — no runtime allocation allowed)
__device__ __half g_xh[(size_t)BTv * Lv * INC];    // x converted to half
__device__ __half g_w1h[(size_t)CAv * INC];        // fc1_w half
__device__ __half g_w2h[(size_t)INC * CAv];        // fc2_w half
__device__ __half g_h0h[(size_t)CAv * MTOT];       // h0, channel-outer [ca][m]
__device__ __half g_h2h[(size_t)CAv * MTOT];       // h2, channel-outer [ca][m]

// GEMM tiling: BM=BN=128, BK=32 (two m16n16k16 steps)
#define BK 32
#define SA 40     // half-row stride for [*][32]-half tiles (80B, mult of 8)
#define SAT 136   // half-row stride for fc2 transposed-A [32][128] (272B, mult of 8)
#define PCM 132   // fc1 C staging col-major ldm (floats, mult of 4)
#define PCR 68    // fc2 C staging row-major ldm (floats, mult of 4)

constexpr int FC1_BUF = 128 * SA * 2;          // A+B halves per stage = 10240
constexpr int FC2_ABUF = 32 * SAT;             // 4352 halves
constexpr int FC2_BBUF = 128 * SA;             // 5120 halves
constexpr int FC2_BUF  = FC2_ABUF + FC2_BBUF;  // 9472 halves
// 40960 B covers: fc1 2*10240 halves (40960B), fc2 2*9472 (37888B),
// fc1 stage 32*132 floats (16896B), fc2 stage 128*68 floats (34816B)
#define SMEM_BYTES 40960

__device__ __forceinline__ void cp16(uint32_t dst, const void* src) {
    asm volatile("cp.async.cg.shared.global [%0], [%1], 16;\n" :: "r"(dst), "l"(src));
}
__device__ __forceinline__ void cp_commit() { asm volatile("cp.async.commit_group;\n"); }
__device__ __forceinline__ void cp_wait0()  { asm volatile("cp.async.wait_group 0;\n"); }
__device__ __forceinline__ uint32_t smem_u32(const void* p) {
    return (uint32_t)__cvta_generic_to_shared(p);
}

// ---------------------------------------------------------------------------
// Converters (fp32 -> fp16), vectorized
// ---------------------------------------------------------------------------
__global__ __launch_bounds__(256) void cvt_kernel(
    const float* __restrict__ src, __half* __restrict__ dst, int n4)
{
    int i = blockIdx.x * 256 + threadIdx.x;
    if (i >= n4) return;
    float4 v = *reinterpret_cast<const float4*>(src + (size_t)i * 4);
    __half2 h0 = __floats2half2_rn(v.x, v.y);
    __half2 h1 = __floats2half2_rn(v.z, v.w);
    uint2 o = { *reinterpret_cast<uint32_t*>(&h0), *reinterpret_cast<uint32_t*>(&h1) };
    *reinterpret_cast<uint2*>(dst + (size_t)i * 4) = o;
}

// ---------------------------------------------------------------------------
// fc1: h0[n(ca), m] = sum_k x[m,k] * w[n,k] + bias[n]   (channel-outer half out)
// ---------------------------------------------------------------------------
__global__ __launch_bounds__(256, 2) void fc1_kernel(const float* __restrict__ bias)
{
    __shared__ __align__(16) unsigned char smem_raw[SMEM_BYTES];
    __half* sh = reinterpret_cast<__half*>(smem_raw);
    float*  sf = reinterpret_cast<float*>(smem_raw);

    const int m0  = blockIdx.y * 128;
    const int n0  = blockIdx.x * 128;
    const int tid = threadIdx.x;
    const int wid = tid >> 5;
    const int wm  = wid & 1;     // 2 warps along M (64 rows each)
    const int wn  = wid >> 1;    // 4 warps along N (32 cols each)

    wmma::fragment<wmma::accumulator, 16, 16, 16, float> acc[4][2];
    #pragma unroll
    for (int i = 0; i < 4; i++)
        #pragma unroll
        for (int j = 0; j < 2; j++)
            wmma::fill_fragment(acc[i][j], 0.0f);

    // Loaders: 512 chunks of 16B per tile per operand; 2 chunks/thread.
    // chunk idx = tid + u*256 : row = idx>>2 (0..127), ch = idx&3 (8 halves each)
    size_t abase[2], bbase[2];
    int lrow[2], lch[2];
    #pragma unroll
    for (int u = 0; u < 2; u++) {
        int idx = tid + u * 256;
        lrow[u] = idx >> 2;
        lch[u]  = idx & 3;
        int m  = m0 + lrow[u];
        int bt = m / NP;
        int pos = m - bt * NP;
        abase[u] = ((size_t)(bt * Lv + 1 + pos)) * INC;
        bbase[u] = (size_t)(n0 + lrow[u]) * INC;
    }

    constexpr int KT = INC / BK;   // 24

    // prefetch tile 0
    {
        uint32_t sA = smem_u32(sh);                 // stage 0: A at 0, B at 128*SA
        uint32_t sB = smem_u32(sh + 128 * SA);
        #pragma unroll
        for (int u = 0; u < 2; u++) {
            cp16(sA + (uint32_t)(lrow[u] * SA + lch[u] * 8) * 2, g_xh + abase[u] + lch[u] * 8);
            cp16(sB + (uint32_t)(lrow[u] * SA + lch[u] * 8) * 2, g_w1h + bbase[u] + lch[u] * 8);
        }
        cp_commit();
    }

    for (int kt = 0; kt < KT; kt++) {
        cp_wait0();
        __syncthreads();

        if (kt + 1 < KT) {
            int k0 = (kt + 1) * BK;
            __half* st = sh + ((kt + 1) & 1) * FC1_BUF;
            uint32_t sA = smem_u32(st);
            uint32_t sB = smem_u32(st + 128 * SA);
            #pragma unroll
            for (int u = 0; u < 2; u++) {
                cp16(sA + (uint32_t)(lrow[u] * SA + lch[u] * 8) * 2, g_xh + abase[u] + k0 + lch[u] * 8);
                cp16(sB + (uint32_t)(lrow[u] * SA + lch[u] * 8) * 2, g_w1h + bbase[u] + k0 + lch[u] * 8);
            }
            cp_commit();
        }

        __half* As = sh + (kt & 1) * FC1_BUF;
        __half* Bs = As + 128 * SA;
        #pragma unroll
        for (int ks = 0; ks < BK; ks += 16) {
            wmma::fragment<wmma::matrix_a, 16, 16, 16, __half, wmma::row_major> af[4];
            wmma::fragment<wmma::matrix_b, 16, 16, 16, __half, wmma::col_major> bf[2];
            #pragma unroll
            for (int i = 0; i < 4; i++)
                wmma::load_matrix_sync(af[i], &As[(wm * 64 + i * 16) * SA + ks], SA);
            #pragma unroll
            for (int j = 0; j < 2; j++)
                wmma::load_matrix_sync(bf[j], &Bs[(wn * 32 + j * 16) * SA + ks], SA);
            #pragma unroll
            for (int i = 0; i < 4; i++)
                #pragma unroll
                for (int j = 0; j < 2; j++)
                    wmma::mma_sync(acc[i][j], af[i], bf[j], acc[i][j]);
        }
    }
    __syncthreads();

    // Epilogue: 4 passes of 32 cols, COL-MAJOR staging (ldm=132); half write-out
    #pragma unroll
    for (int pass = 0; pass < 4; pass++) {
        if (wn == pass) {
            #pragma unroll
            for (int i = 0; i < 4; i++)
                #pragma unroll
                for (int j = 0; j < 2; j++)
                    wmma::store_matrix_sync(&sf[(j * 16) * PCM + wm * 64 + i * 16],
                                            acc[i][j], PCM, wmma::mem_col_major);
        }
        __syncthreads();
        #pragma unroll
        for (int it = 0; it < 16; it++) {
            int e = tid + it * 256;
            int col = e >> 7, r = e & 127;
            int n = n0 + pass * 32 + col;
            g_h0h[(size_t)n * MTOT + m0 + r] =
                __float2half(sf[col * PCM + r] + __ldg(&bias[n]));
        }
        __syncthreads();
    }
}

// ---------------------------------------------------------------------------
// Fused convs (half in/out, fp32 math): combined 27-tap stencil + identity,
// then temporal proj conv + residual. One block per (b, ca).
// ---------------------------------------------------------------------------
__global__ __launch_bounds__(256) void conv_fused_kernel(
    const float* __restrict__ w1, const float* __restrict__ b1,
    const float* __restrict__ w2, const float* __restrict__ b2,
    const float* __restrict__ w3, const float* __restrict__ b3,
    const float* __restrict__ wp, const float* __restrict__ pb)
{
    __shared__ float s0[TILE3D];
    __shared__ float s1[TILE3D];

    const int tid = threadIdx.x;
    const int ca  = blockIdx.x % CAv;
    const int b   = blockIdx.x / CAv;
    const size_t base = (size_t)ca * MTOT + (size_t)b * TILE3D;

    for (int i = tid * 4; i < TILE3D; i += 1024) {
        uint2 p = *reinterpret_cast<const uint2*>(&g_h0h[base + i]);
        __half2 h0 = *reinterpret_cast<__half2*>(&p.x);
        __half2 h1 = *reinterpret_cast<__half2*>(&p.y);
        float2 f0 = __half22float2(h0);
        float2 f1 = __half22float2(h1);
        s0[i] = f0.x; s0[i + 1] = f0.y; s0[i + 2] = f1.x; s0[i + 3] = f1.y;
    }

    float wc[27];
    #pragma unroll
    for (int j = 0; j < 27; j++) wc[j] = w3[ca * 27 + j];
    #pragma unroll
    for (int j = 0; j < 9; j++)  wc[9 + j] += w2[ca * 9 + j];
    #pragma unroll
    for (int dt = 0; dt < 3; dt++) wc[dt * 9 + 4] += w1[ca * 3 + dt];
    const float bias3 = (b1[ca] + b2[ca] + b3[ca]) * (1.0f / 3.0f);
    const float wp0 = wp[ca * 3], wp1 = wp[ca * 3 + 1], wp2 = wp[ca * 3 + 2];
    const float pbias = pb[ca];

    __syncthreads();

    for (int e = tid; e < TILE3D; e += 256) {
        int t   = e / NP;
        int pos = e - t * NP;
        int y   = pos / Wv;
        int x   = pos - y * Wv;
        float acc = 0.0f;
        #pragma unroll
        for (int dt = -1; dt <= 1; dt++) {
            int tt = t + dt;
            if ((unsigned)tt >= (unsigned)Tv) continue;
            #pragma unroll
            for (int dy = -1; dy <= 1; dy++) {
                int yy = y + dy;
                if ((unsigned)yy >= (unsigned)Hv) continue;
                #pragma unroll
                for (int dx = -1; dx <= 1; dx++) {
                    int xx = x + dx;
                    if ((unsigned)xx >= (unsigned)Wv) continue;
                    acc += wc[(dt + 1) * 9 + (dy + 1) * 3 + (dx + 1)]
                           * s0[tt * NP + yy * Wv + xx];
                }
            }
        }
        s1[e] = acc * (1.0f / 3.0f) + bias3 + s0[e];
    }
    __syncthreads();

    for (int e = tid; e < TILE3D; e += 256) {
        int t = e / NP;
        float acc = pbias;
        if (t > 0)      acc += wp0 * s1[e - NP];
        acc += wp1 * s1[e];
        if (t < Tv - 1) acc += wp2 * s1[e + NP];
        g_h2h[base + e] = __float2half(s1[e] + acc);
    }
}

// ---------------------------------------------------------------------------
// fc2: out[m, n] = x[m, n] + sum_k h2[k, m] * w[n, k] + bias[n]
//   A = transposed h2 (col-major fragments), all-half operands
// ---------------------------------------------------------------------------
__global__ __launch_bounds__(256, 2) void fc2_kernel(
    const float* __restrict__ bias,
    const float* __restrict__ x,
    float* __restrict__ out)
{
    __shared__ __align__(16) unsigned char smem_raw[SMEM_BYTES];
    __half* sh = reinterpret_cast<__half*>(smem_raw);
    float*  sf = reinterpret_cast<float*>(smem_raw);

    const int m0  = blockIdx.y * 128;
    const int n0  = blockIdx.x * 128;
    const int tid = threadIdx.x;
    const int wid = tid >> 5;
    const int wm  = wid & 1;     // 2 warps along M (64 each)
    const int wn  = wid >> 1;    // 4 warps along N (32 each)

    wmma::fragment<wmma::accumulator, 16, 16, 16, float> acc[4][2];
    #pragma unroll
    for (int i = 0; i < 4; i++)
        #pragma unroll
        for (int j = 0; j < 2; j++)
            wmma::fill_fragment(acc[i][j], 0.0f);

    // A: 512 chunks: kr = idx>>4 (0..31), mc = idx&15 (8 halves each)
    // B: 512 chunks: row = idx>>2 (0..127), ch = idx&3
    int akr[2], amc[2], brow[2], bch[2];
    size_t bbase[2];
    #pragma unroll
    for (int u = 0; u < 2; u++) {
        int idx = tid + u * 256;
        akr[u] = idx >> 4;
        amc[u] = idx & 15;
        brow[u] = idx >> 2;
        bch[u]  = idx & 3;
        bbase[u] = (size_t)(n0 + brow[u]) * CAv;
    }

    constexpr int KT = CAv / BK;   // 12

    {
        uint32_t sA = smem_u32(sh);
        uint32_t sB = smem_u32(sh + FC2_ABUF);
        #pragma unroll
        for (int u = 0; u < 2; u++) {
            cp16(sA + (uint32_t)(akr[u] * SAT + amc[u] * 8) * 2,
                 g_h2h + (size_t)akr[u] * MTOT + m0 + amc[u] * 8);
            cp16(sB + (uint32_t)(brow[u] * SA + bch[u] * 8) * 2,
                 g_w2h + bbase[u] + bch[u] * 8);
        }
        cp_commit();
    }

    for (int kt = 0; kt < KT; kt++) {
        cp_wait0();
        __syncthreads();

        if (kt + 1 < KT) {
            int k0 = (kt + 1) * BK;
            __half* st = sh + ((kt + 1) & 1) * FC2_BUF;
            uint32_t sA = smem_u32(st);
            uint32_t sB = smem_u32(st + FC2_ABUF);
            #pragma unroll
            for (int u = 0; u < 2; u++) {
                cp16(sA + (uint32_t)(akr[u] * SAT + amc[u] * 8) * 2,
                     g_h2h + (size_t)(k0 + akr[u]) * MTOT + m0 + amc[u] * 8);
                cp16(sB + (uint32_t)(brow[u] * SA + bch[u] * 8) * 2,
                     g_w2h + bbase[u] + k0 + bch[u] * 8);
            }
            cp_commit();
        }

        __half* As = sh + (kt & 1) * FC2_BUF;
        __half* Bs = As + FC2_ABUF;
        #pragma unroll
        for (int ks = 0; ks < BK; ks += 16) {
            wmma::fragment<wmma::matrix_a, 16, 16, 16, __half, wmma::col_major> af[4];
            wmma::fragment<wmma::matrix_b, 16, 16, 16, __half, wmma::col_major> bf[2];
            #pragma unroll
            for (int i = 0; i < 4; i++)
                wmma::load_matrix_sync(af[i], &As[ks * SAT + wm * 64 + i * 16], SAT);
            #pragma unroll
            for (int j = 0; j < 2; j++)
                wmma::load_matrix_sync(bf[j], &Bs[(wn * 32 + j * 16) * SA + ks], SA);
            #pragma unroll
            for (int i = 0; i < 4; i++)
                #pragma unroll
                for (int j = 0; j < 2; j++)
                    wmma::mma_sync(acc[i][j], af[i], bf[j], acc[i][j]);
        }
    }
    __syncthreads();

    // Epilogue: 4 passes of 32 cols, ROW-MAJOR staging (ldm=68); out += x + bias
    #pragma unroll
    for (int pass = 0; pass < 4; pass++) {
        if (wn == pass) {
            #pragma unroll
            for (int i = 0; i < 4; i++)
                #pragma unroll
                for (int j = 0; j < 2; j++)
                    wmma::store_matrix_sync(&sf[(wm * 64 + i * 16) * PCR + j * 16],
                                            acc[i][j], PCR, wmma::mem_row_major);
        }
        __syncthreads();
        #pragma unroll
        for (int it = 0; it < 16; it++) {
            int e = tid + it * 256;
            int c = e & 31, r = e >> 5;
            int m = m0 + r;
            int bt = m / NP;
            int pos = m - bt * NP;
            int n = n0 + pass * 32 + c;
            size_t off = ((size_t)(bt * Lv + 1 + pos)) * INC + n;
            out[off] = x[off] + sf[r * PCR + c] + __ldg(&bias[n]);
        }
        __syncthreads();
    }
}

// ---------------------------------------------------------------------------
__global__ __launch_bounds__(256) void cls_kernel(
    const float* __restrict__ x, float* __restrict__ out)
{
    int i = blockIdx.x * 256 + threadIdx.x;
    if (i >= BTv * INC) return;
    int bt = i / INC, c = i % INC;
    size_t off = (size_t)bt * Lv * INC + c;
    out[off] = x[off];
}

// ---------------------------------------------------------------------------
extern "C" void kernel_launch(void* const* d_in, const int* in_sizes, int n_in,
                              void* d_out, int out_size)
{
    const float* x     = (const float*)d_in[0];
    const float* fc1_w = (const float*)d_in[1];
    const float* fc1_b = (const float*)d_in[2];
    const float* c1w   = (const float*)d_in[3];
    const float* c1b   = (const float*)d_in[4];
    const float* c2w   = (const float*)d_in[5];
    const float* c2b   = (const float*)d_in[6];
    const float* c3w   = (const float*)d_in[7];
    const float* c3b   = (const float*)d_in[8];
    const float* pw    = (const float*)d_in[9];
    const float* pb    = (const float*)d_in[10];
    const float* fc2_w = (const float*)d_in[11];
    const float* fc2_b = (const float*)d_in[12];
    float* out = (float*)d_out;

    __half* xh;  cudaGetSymbolAddress((void**)&xh,  g_xh);
    __half* w1h; cudaGetSymbolAddress((void**)&w1h, g_w1h);
    __half* w2h; cudaGetSymbolAddress((void**)&w2h, g_w2h);

    // fp32 -> fp16 conversions
    int nx4 = BTv * Lv * INC / 4;
    cvt_kernel<<<(nx4 + 255) / 256, 256>>>(x, xh, nx4);
    int n14 = CAv * INC / 4;
    cvt_kernel<<<(n14 + 255) / 256, 256>>>(fc1_w, w1h, n14);
    int n24 = INC * CAv / 4;
    cvt_kernel<<<(n24 + 255) / 256, 256>>>(fc2_w, w2h, n24);

    dim3 g1(CAv / 128, MTOT / 128);   // (3, 196)
    fc1_kernel<<<g1, 256>>>(fc1_b);

    conv_fused_kernel<<<CAv * (BTv / Tv), 256>>>(c1w, c1b, c2w, c2b, c3w, c3b, pw, pb);

    dim3 g2(INC / 128, MTOT / 128);   // (6, 196)
    fc2_kernel<<<g2, 256>>>(fc2_b, x, out);

    cls_kernel<<<(BTv * INC + 255) / 256, 256>>>(x, out);
}

// round 11
// speedup vs baseline: 2.0674x; 1.0226x over previous
#include <cuda_runtime.h>
#include <cuda_fp16.h>
#include <mma.h>
#include <cstdint>

using namespace nvcuda;

constexpr int INC  = 768;
constexpr int CAv  = 384;
constexpr int BTv  = 128;
constexpr int Tv   = 16;
constexpr int Hv   = 14;
constexpr int Wv   = 14;
constexpr int Lv   = 197;
constexpr int NP   = 196;
constexpr int MTOT = BTv * NP;       // 25088
constexpr int TILE3D = Tv * NP;      // 3136

// Scratch (device globals — no runtime allocation allowed)
__device__ __half g_xh[(size_t)BTv * Lv * INC];
__device__ __half g_w1h[(size_t)CAv * INC];
__device__ __half g_w2h[(size_t)INC * CAv];
__device__ __half g_h0h[(size_t)CAv * MTOT];       // channel-outer [ca][m]
__device__ __half g_h2h[(size_t)CAv * MTOT];       // channel-outer [ca][m]

// GEMM tiling: BM=BN=128, BK=64 (four m16n16k16 steps per tile)
#define BK 64
#define SA 72     // half-row stride for [*][64]-half K tiles (144B)
#define SAT 136   // half-row stride for fc2 transposed-A [64][128]
#define PCM 132   // fc1 C staging col-major ldm (floats)
#define PCR 68    // fc2 C staging row-major ldm (floats)

constexpr int FC1_ABUF = 128 * SA;                 // 9216 halves
constexpr int FC1_BUF  = 2 * FC1_ABUF;             // A+B per stage = 18432 halves
constexpr int FC1_SMEM = 2 * FC1_BUF * 2;          // 73728 B
constexpr int FC2_ABUF = BK * SAT;                 // 8704 halves
constexpr int FC2_BBUF = 128 * SA;                 // 9216 halves
constexpr int FC2_BUF  = FC2_ABUF + FC2_BBUF;      // 17920 halves
constexpr int FC2_SMEM = 2 * FC2_BUF * 2;          // 71680 B

__device__ __forceinline__ void cp16(uint32_t dst, const void* src) {
    asm volatile("cp.async.cg.shared.global [%0], [%1], 16;\n" :: "r"(dst), "l"(src));
}
__device__ __forceinline__ void cp_commit() { asm volatile("cp.async.commit_group;\n"); }
__device__ __forceinline__ void cp_wait0()  { asm volatile("cp.async.wait_group 0;\n"); }
__device__ __forceinline__ uint32_t smem_u32(const void* p) {
    return (uint32_t)__cvta_generic_to_shared(p);
}

// ---------------------------------------------------------------------------
// Merged fp32 -> fp16 converter: covers x, fc1_w, fc2_w in one launch
// ---------------------------------------------------------------------------
constexpr int NX4 = BTv * Lv * INC / 4;   // x chunks (float4)
constexpr int NW4 = CAv * INC / 4;        // per-weight chunks

__global__ __launch_bounds__(256) void cvt_all_kernel(
    const float* __restrict__ x, const float* __restrict__ w1,
    const float* __restrict__ w2)
{
    int i = blockIdx.x * 256 + threadIdx.x;
    const float* src; __half* dst; size_t off;
    if (i < NX4)                { src = x;  dst = g_xh;  off = (size_t)i; }
    else if (i < NX4 + NW4)     { src = w1; dst = g_w1h; off = (size_t)(i - NX4); }
    else if (i < NX4 + 2 * NW4) { src = w2; dst = g_w2h; off = (size_t)(i - NX4 - NW4); }
    else return;
    float4 v = *reinterpret_cast<const float4*>(src + off * 4);
    __half2 h0 = __floats2half2_rn(v.x, v.y);
    __half2 h1 = __floats2half2_rn(v.z, v.w);
    uint2 o = { *reinterpret_cast<uint32_t*>(&h0), *reinterpret_cast<uint32_t*>(&h1) };
    *reinterpret_cast<uint2*>(dst + off * 4) = o;
}

// ---------------------------------------------------------------------------
// fc1: h0[n(ca), m] = sum_k x[m,k] * w[n,k] + bias[n]  (channel-outer half out)
// ---------------------------------------------------------------------------
__global__ __launch_bounds__(256, 2) void fc1_kernel(const float* __restrict__ bias)
{
    extern __shared__ __align__(16) unsigned char smem_raw[];
    __half* sh = reinterpret_cast<__half*>(smem_raw);
    float*  sf = reinterpret_cast<float*>(smem_raw);

    const int m0  = blockIdx.y * 128;
    const int n0  = blockIdx.x * 128;
    const int tid = threadIdx.x;
    const int wid = tid >> 5;
    const int wm  = wid & 1;     // 2 warps along M (64 rows)
    const int wn  = wid >> 1;    // 4 warps along N (32 cols)

    wmma::fragment<wmma::accumulator, 16, 16, 16, float> acc[4][2];
    #pragma unroll
    for (int i = 0; i < 4; i++)
        #pragma unroll
        for (int j = 0; j < 2; j++)
            wmma::fill_fragment(acc[i][j], 0.0f);

    // Loaders: 1024 chunks of 16B per operand per tile; 4 chunks/thread.
    // idx = tid + u*256 : row = idx>>3 (0..127), ch = idx&7 (8 halves)
    size_t abase[4], bbase[4];
    int lrow[4], lch[4];
    #pragma unroll
    for (int u = 0; u < 4; u++) {
        int idx = tid + u * 256;
        lrow[u] = idx >> 3;
        lch[u]  = idx & 7;
        int m  = m0 + lrow[u];
        int bt = m / NP;
        int pos = m - bt * NP;
        abase[u] = ((size_t)(bt * Lv + 1 + pos)) * INC;
        bbase[u] = (size_t)(n0 + lrow[u]) * INC;
    }

    constexpr int KT = INC / BK;   // 12

    {
        uint32_t sA = smem_u32(sh);
        uint32_t sB = smem_u32(sh + FC1_ABUF);
        #pragma unroll
        for (int u = 0; u < 4; u++) {
            uint32_t d = (uint32_t)(lrow[u] * SA + lch[u] * 8) * 2;
            cp16(sA + d, g_xh  + abase[u] + lch[u] * 8);
            cp16(sB + d, g_w1h + bbase[u] + lch[u] * 8);
        }
        cp_commit();
    }

    for (int kt = 0; kt < KT; kt++) {
        cp_wait0();
        __syncthreads();

        if (kt + 1 < KT) {
            int k0 = (kt + 1) * BK;
            __half* st = sh + ((kt + 1) & 1) * FC1_BUF;
            uint32_t sA = smem_u32(st);
            uint32_t sB = smem_u32(st + FC1_ABUF);
            #pragma unroll
            for (int u = 0; u < 4; u++) {
                uint32_t d = (uint32_t)(lrow[u] * SA + lch[u] * 8) * 2;
                cp16(sA + d, g_xh  + abase[u] + k0 + lch[u] * 8);
                cp16(sB + d, g_w1h + bbase[u] + k0 + lch[u] * 8);
            }
            cp_commit();
        }

        __half* As = sh + (kt & 1) * FC1_BUF;
        __half* Bs = As + FC1_ABUF;
        #pragma unroll
        for (int ks = 0; ks < BK; ks += 16) {
            wmma::fragment<wmma::matrix_a, 16, 16, 16, __half, wmma::row_major> af[4];
            wmma::fragment<wmma::matrix_b, 16, 16, 16, __half, wmma::col_major> bf[2];
            #pragma unroll
            for (int i = 0; i < 4; i++)
                wmma::load_matrix_sync(af[i], &As[(wm * 64 + i * 16) * SA + ks], SA);
            #pragma unroll
            for (int j = 0; j < 2; j++)
                wmma::load_matrix_sync(bf[j], &Bs[(wn * 32 + j * 16) * SA + ks], SA);
            #pragma unroll
            for (int i = 0; i < 4; i++)
                #pragma unroll
                for (int j = 0; j < 2; j++)
                    wmma::mma_sync(acc[i][j], af[i], bf[j], acc[i][j]);
        }
    }
    __syncthreads();

    // Epilogue: 4 passes of 32 cols, COL-MAJOR staging (ldm=132); half out
    #pragma unroll
    for (int pass = 0; pass < 4; pass++) {
        if (wn == pass) {
            #pragma unroll
            for (int i = 0; i < 4; i++)
                #pragma unroll
                for (int j = 0; j < 2; j++)
                    wmma::store_matrix_sync(&sf[(j * 16) * PCM + wm * 64 + i * 16],
                                            acc[i][j], PCM, wmma::mem_col_major);
        }
        __syncthreads();
        #pragma unroll
        for (int it = 0; it < 16; it++) {
            int e = tid + it * 256;
            int col = e >> 7, r = e & 127;
            int n = n0 + pass * 32 + col;
            g_h0h[(size_t)n * MTOT + m0 + r] =
                __float2half(sf[col * PCM + r] + __ldg(&bias[n]));
        }
        __syncthreads();
    }
}

// ---------------------------------------------------------------------------
// Fused convs (half in/out, fp32 math)
// ---------------------------------------------------------------------------
__global__ __launch_bounds__(256) void conv_fused_kernel(
    const float* __restrict__ w1, const float* __restrict__ b1,
    const float* __restrict__ w2, const float* __restrict__ b2,
    const float* __restrict__ w3, const float* __restrict__ b3,
    const float* __restrict__ wp, const float* __restrict__ pb)
{
    __shared__ float s0[TILE3D];
    __shared__ float s1[TILE3D];

    const int tid = threadIdx.x;
    const int ca  = blockIdx.x % CAv;
    const int b   = blockIdx.x / CAv;
    const size_t base = (size_t)ca * MTOT + (size_t)b * TILE3D;

    for (int i = tid * 4; i < TILE3D; i += 1024) {
        uint2 p = *reinterpret_cast<const uint2*>(&g_h0h[base + i]);
        __half2 h0 = *reinterpret_cast<__half2*>(&p.x);
        __half2 h1 = *reinterpret_cast<__half2*>(&p.y);
        float2 f0 = __half22float2(h0);
        float2 f1 = __half22float2(h1);
        s0[i] = f0.x; s0[i + 1] = f0.y; s0[i + 2] = f1.x; s0[i + 3] = f1.y;
    }

    float wc[27];
    #pragma unroll
    for (int j = 0; j < 27; j++) wc[j] = w3[ca * 27 + j];
    #pragma unroll
    for (int j = 0; j < 9; j++)  wc[9 + j] += w2[ca * 9 + j];
    #pragma unroll
    for (int dt = 0; dt < 3; dt++) wc[dt * 9 + 4] += w1[ca * 3 + dt];
    const float bias3 = (b1[ca] + b2[ca] + b3[ca]) * (1.0f / 3.0f);
    const float wp0 = wp[ca * 3], wp1 = wp[ca * 3 + 1], wp2 = wp[ca * 3 + 2];
    const float pbias = pb[ca];

    __syncthreads();

    for (int e = tid; e < TILE3D; e += 256) {
        int t   = e / NP;
        int pos = e - t * NP;
        int y   = pos / Wv;
        int x   = pos - y * Wv;
        float acc = 0.0f;
        #pragma unroll
        for (int dt = -1; dt <= 1; dt++) {
            int tt = t + dt;
            if ((unsigned)tt >= (unsigned)Tv) continue;
            #pragma unroll
            for (int dy = -1; dy <= 1; dy++) {
                int yy = y + dy;
                if ((unsigned)yy >= (unsigned)Hv) continue;
                #pragma unroll
                for (int dx = -1; dx <= 1; dx++) {
                    int xx = x + dx;
                    if ((unsigned)xx >= (unsigned)Wv) continue;
                    acc += wc[(dt + 1) * 9 + (dy + 1) * 3 + (dx + 1)]
                           * s0[tt * NP + yy * Wv + xx];
                }
            }
        }
        s1[e] = acc * (1.0f / 3.0f) + bias3 + s0[e];
    }
    __syncthreads();

    for (int e = tid; e < TILE3D; e += 256) {
        int t = e / NP;
        float acc = pbias;
        if (t > 0)      acc += wp0 * s1[e - NP];
        acc += wp1 * s1[e];
        if (t < Tv - 1) acc += wp2 * s1[e + NP];
        g_h2h[base + e] = __float2half(s1[e] + acc);
    }
}

// ---------------------------------------------------------------------------
// fc2: out[m, n] = x[m, n] + sum_k h2[k, m] * w[n, k] + bias[n]
// ---------------------------------------------------------------------------
__global__ __launch_bounds__(256, 2) void fc2_kernel(
    const float* __restrict__ bias,
    const float* __restrict__ x,
    float* __restrict__ out)
{
    extern __shared__ __align__(16) unsigned char smem_raw[];
    __half* sh = reinterpret_cast<__half*>(smem_raw);
    float*  sf = reinterpret_cast<float*>(smem_raw);

    const int m0  = blockIdx.y * 128;
    const int n0  = blockIdx.x * 128;
    const int tid = threadIdx.x;
    const int wid = tid >> 5;
    const int wm  = wid & 1;
    const int wn  = wid >> 1;

    wmma::fragment<wmma::accumulator, 16, 16, 16, float> acc[4][2];
    #pragma unroll
    for (int i = 0; i < 4; i++)
        #pragma unroll
        for (int j = 0; j < 2; j++)
            wmma::fill_fragment(acc[i][j], 0.0f);

    // A: 1024 chunks: kr = idx>>4 (0..63), mc = idx&15. B: row=idx>>3, ch=idx&7
    int akr[4], amc[4], brow[4], bch[4];
    size_t bbase[4];
    #pragma unroll
    for (int u = 0; u < 4; u++) {
        int idx = tid + u * 256;
        akr[u] = idx >> 4;
        amc[u] = idx & 15;
        brow[u] = idx >> 3;
        bch[u]  = idx & 7;
        bbase[u] = (size_t)(n0 + brow[u]) * CAv;
    }

    constexpr int KT = CAv / BK;   // 6

    {
        uint32_t sA = smem_u32(sh);
        uint32_t sB = smem_u32(sh + FC2_ABUF);
        #pragma unroll
        for (int u = 0; u < 4; u++) {
            cp16(sA + (uint32_t)(akr[u] * SAT + amc[u] * 8) * 2,
                 g_h2h + (size_t)akr[u] * MTOT + m0 + amc[u] * 8);
            cp16(sB + (uint32_t)(brow[u] * SA + bch[u] * 8) * 2,
                 g_w2h + bbase[u] + bch[u] * 8);
        }
        cp_commit();
    }

    for (int kt = 0; kt < KT; kt++) {
        cp_wait0();
        __syncthreads();

        if (kt + 1 < KT) {
            int k0 = (kt + 1) * BK;
            __half* st = sh + ((kt + 1) & 1) * FC2_BUF;
            uint32_t sA = smem_u32(st);
            uint32_t sB = smem_u32(st + FC2_ABUF);
            #pragma unroll
            for (int u = 0; u < 4; u++) {
                cp16(sA + (uint32_t)(akr[u] * SAT + amc[u] * 8) * 2,
                     g_h2h + (size_t)(k0 + akr[u]) * MTOT + m0 + amc[u] * 8);
                cp16(sB + (uint32_t)(brow[u] * SA + bch[u] * 8) * 2,
                     g_w2h + bbase[u] + k0 + bch[u] * 8);
            }
            cp_commit();
        }

        __half* As = sh + (kt & 1) * FC2_BUF;
        __half* Bs = As + FC2_ABUF;
        #pragma unroll
        for (int ks = 0; ks < BK; ks += 16) {
            wmma::fragment<wmma::matrix_a, 16, 16, 16, __half, wmma::col_major> af[4];
            wmma::fragment<wmma::matrix_b, 16, 16, 16, __half, wmma::col_major> bf[2];
            #pragma unroll
            for (int i = 0; i < 4; i++)
                wmma::load_matrix_sync(af[i], &As[ks * SAT + wm * 64 + i * 16], SAT);
            #pragma unroll
            for (int j = 0; j < 2; j++)
                wmma::load_matrix_sync(bf[j], &Bs[(wn * 32 + j * 16) * SA + ks], SA);
            #pragma unroll
            for (int i = 0; i < 4; i++)
                #pragma unroll
                for (int j = 0; j < 2; j++)
                    wmma::mma_sync(acc[i][j], af[i], bf[j], acc[i][j]);
        }
    }
    __syncthreads();

    // Epilogue: 4 passes of 32 cols, ROW-MAJOR staging (ldm=68)
    #pragma unroll
    for (int pass = 0; pass < 4; pass++) {
        if (wn == pass) {
            #pragma unroll
            for (int i = 0; i < 4; i++)
                #pragma unroll
                for (int j = 0; j < 2; j++)
                    wmma::store_matrix_sync(&sf[(wm * 64 + i * 16) * PCR + j * 16],
                                            acc[i][j], PCR, wmma::mem_row_major);
        }
        __syncthreads();
        #pragma unroll
        for (int it = 0; it < 16; it++) {
            int e = tid + it * 256;
            int c = e & 31, r = e >> 5;
            int m = m0 + r;
            int bt = m / NP;
            int pos = m - bt * NP;
            int n = n0 + pass * 32 + c;
            size_t off = ((size_t)(bt * Lv + 1 + pos)) * INC + n;
            out[off] = x[off] + sf[r * PCR + c] + __ldg(&bias[n]);
        }
        __syncthreads();
    }
}

// ---------------------------------------------------------------------------
__global__ __launch_bounds__(256) void cls_kernel(
    const float* __restrict__ x, float* __restrict__ out)
{
    int i = blockIdx.x * 256 + threadIdx.x;
    if (i >= BTv * INC) return;
    int bt = i / INC, c = i % INC;
    size_t off = (size_t)bt * Lv * INC + c;
    out[off] = x[off];
}

// ---------------------------------------------------------------------------
extern "C" void kernel_launch(void* const* d_in, const int* in_sizes, int n_in,
                              void* d_out, int out_size)
{
    const float* x     = (const float*)d_in[0];
    const float* fc1_w = (const float*)d_in[1];
    const float* fc1_b = (const float*)d_in[2];
    const float* c1w   = (const float*)d_in[3];
    const float* c1b   = (const float*)d_in[4];
    const float* c2w   = (const float*)d_in[5];
    const float* c2b   = (const float*)d_in[6];
    const float* c3w   = (const float*)d_in[7];
    const float* c3b   = (const float*)d_in[8];
    const float* pw    = (const float*)d_in[9];
    const float* pb    = (const float*)d_in[10];
    const float* fc2_w = (const float*)d_in[11];
    const float* fc2_b = (const float*)d_in[12];
    float* out = (float*)d_out;

    cudaFuncSetAttribute(fc1_kernel, cudaFuncAttributeMaxDynamicSharedMemorySize, FC1_SMEM);
    cudaFuncSetAttribute(fc2_kernel, cudaFuncAttributeMaxDynamicSharedMemorySize, FC2_SMEM);

    int ncvt = NX4 + 2 * NW4;
    cvt_all_kernel<<<(ncvt + 255) / 256, 256>>>(x, fc1_w, fc2_w);

    dim3 g1(CAv / 128, MTOT / 128);   // (3, 196)
    fc1_kernel<<<g1, 256, FC1_SMEM>>>(fc1_b);

    conv_fused_kernel<<<CAv * (BTv / Tv), 256>>>(c1w, c1b, c2w, c2b, c3w, c3b, pw, pb);

    dim3 g2(INC / 128, MTOT / 128);   // (6, 196)
    fc2_kernel<<<g2, 256, FC2_SMEM>>>(fc2_b, x, out);

    cls_kernel<<<(BTv * INC + 255) / 256, 256>>>(x, out);
}

// round 12
// speedup vs baseline: 2.4980x; 1.2083x over previous
#include <cuda_runtime.h>
#include <cuda_fp16.h>
#include <mma.h>
#include <cstdint>

using namespace nvcuda;

constexpr int INC  = 768;
constexpr int CAv  = 384;
constexpr int BTv  = 128;
constexpr int Tv   = 16;
constexpr int Hv   = 14;
constexpr int Wv   = 14;
constexpr int Lv   = 197;
constexpr int NP   = 196;
constexpr int MTOT = BTv * NP;       // 25088
constexpr int TILE3D = Tv * NP;      // 3136

// Scratch (device globals — no runtime allocation allowed)
__device__ __half g_xh[(size_t)BTv * Lv * INC];
__device__ __half g_w1h[(size_t)CAv * INC];
__device__ __half g_w2h[(size_t)INC * CAv];
__device__ __half g_h0h[(size_t)CAv * MTOT];       // channel-outer [ca][m]
__device__ __half g_h2h[(size_t)CAv * MTOT];       // channel-outer [ca][m]

// GEMM tiling: BM=BN=128, BK=64, 3-stage cp.async pipeline
#define BK 64
#define SA 72     // half-row stride for [*][64]-half K tiles (144B)
#define SAT 136   // half-row stride for fc2 transposed-A [64][128]
#define PCM 132   // C staging ldm (floats, mult of 4)

constexpr int FC1_ABUF = 128 * SA;                 // 9216 halves
constexpr int FC1_BUF  = 2 * FC1_ABUF;             // A+B per stage = 18432 halves
constexpr int FC1_SMEM = 3 * FC1_BUF * 2;          // 110592 B
constexpr int FC2_ABUF = BK * SAT;                 // 8704 halves
constexpr int FC2_BBUF = 128 * SA;                 // 9216 halves
constexpr int FC2_BUF  = FC2_ABUF + FC2_BBUF;      // 17920 halves
constexpr int FC2_SMEM = 3 * FC2_BUF * 2;          // 107520 B
// epilogue staging: 128*132 floats = 67584 B — fits inside either

__device__ __forceinline__ void cp16(uint32_t dst, const void* src) {
    asm volatile("cp.async.cg.shared.global [%0], [%1], 16;\n" :: "r"(dst), "l"(src));
}
__device__ __forceinline__ void cp_commit() { asm volatile("cp.async.commit_group;\n"); }
__device__ __forceinline__ void cp_wait1()  { asm volatile("cp.async.wait_group 1;\n"); }
__device__ __forceinline__ uint32_t smem_u32(const void* p) {
    return (uint32_t)__cvta_generic_to_shared(p);
}

// ---------------------------------------------------------------------------
// Merged fp32 -> fp16 converter (x, fc1_w, fc2_w)
// ---------------------------------------------------------------------------
constexpr int NX4 = BTv * Lv * INC / 4;
constexpr int NW4 = CAv * INC / 4;

__global__ __launch_bounds__(256) void cvt_all_kernel(
    const float* __restrict__ x, const float* __restrict__ w1,
    const float* __restrict__ w2)
{
    int i = blockIdx.x * 256 + threadIdx.x;
    const float* src; __half* dst; size_t off;
    if (i < NX4)                { src = x;  dst = g_xh;  off = (size_t)i; }
    else if (i < NX4 + NW4)     { src = w1; dst = g_w1h; off = (size_t)(i - NX4); }
    else if (i < NX4 + 2 * NW4) { src = w2; dst = g_w2h; off = (size_t)(i - NX4 - NW4); }
    else return;
    float4 v = *reinterpret_cast<const float4*>(src + off * 4);
    __half2 h0 = __floats2half2_rn(v.x, v.y);
    __half2 h1 = __floats2half2_rn(v.z, v.w);
    uint2 o = { *reinterpret_cast<uint32_t*>(&h0), *reinterpret_cast<uint32_t*>(&h1) };
    *reinterpret_cast<uint2*>(dst + off * 4) = o;
}

// ---------------------------------------------------------------------------
// fc1: h0[n(ca), m] = sum_k x[m,k] * w[n,k] + bias[n]  (channel-outer half out)
// ---------------------------------------------------------------------------
__global__ __launch_bounds__(256, 2) void fc1_kernel(const float* __restrict__ bias)
{
    extern __shared__ __align__(16) unsigned char smem_raw[];
    __half* sh = reinterpret_cast<__half*>(smem_raw);
    float*  sf = reinterpret_cast<float*>(smem_raw);

    const int m0  = blockIdx.y * 128;
    const int n0  = blockIdx.x * 128;
    const int tid = threadIdx.x;
    const int wid = tid >> 5;
    const int wm  = wid & 1;     // 2 warps along M (64 rows)
    const int wn  = wid >> 1;    // 4 warps along N (32 cols)

    wmma::fragment<wmma::accumulator, 16, 16, 16, float> acc[4][2];
    #pragma unroll
    for (int i = 0; i < 4; i++)
        #pragma unroll
        for (int j = 0; j < 2; j++)
            wmma::fill_fragment(acc[i][j], 0.0f);

    // Loaders: 1024 x 16B chunks per operand per tile; 4 chunks/thread
    size_t abase[4], bbase[4];
    int lrow[4], lch[4];
    #pragma unroll
    for (int u = 0; u < 4; u++) {
        int idx = tid + u * 256;
        lrow[u] = idx >> 3;
        lch[u]  = idx & 7;
        int m  = m0 + lrow[u];
        int bt = m / NP;
        int pos = m - bt * NP;
        abase[u] = ((size_t)(bt * Lv + 1 + pos)) * INC;
        bbase[u] = (size_t)(n0 + lrow[u]) * INC;
    }

    constexpr int KT = INC / BK;   // 12

    // Prologue: tiles 0 and 1 into stages 0, 1
    #pragma unroll
    for (int p = 0; p < 2; p++) {
        __half* st = sh + p * FC1_BUF;
        uint32_t sA = smem_u32(st);
        uint32_t sB = smem_u32(st + FC1_ABUF);
        int k0 = p * BK;
        #pragma unroll
        for (int u = 0; u < 4; u++) {
            uint32_t d = (uint32_t)(lrow[u] * SA + lch[u] * 8) * 2;
            cp16(sA + d, g_xh  + abase[u] + k0 + lch[u] * 8);
            cp16(sB + d, g_w1h + bbase[u] + k0 + lch[u] * 8);
        }
        cp_commit();
    }

    for (int kt = 0; kt < KT; kt++) {
        cp_wait1();               // oldest pending (tile kt) complete
        __syncthreads();

        // Prefetch tile kt+2 (buffer (kt+2)%3 was consumed in iter kt-1)
        if (kt + 2 < KT) {
            int k0 = (kt + 2) * BK;
            __half* st = sh + ((kt + 2) % 3) * FC1_BUF;
            uint32_t sA = smem_u32(st);
            uint32_t sB = smem_u32(st + FC1_ABUF);
            #pragma unroll
            for (int u = 0; u < 4; u++) {
                uint32_t d = (uint32_t)(lrow[u] * SA + lch[u] * 8) * 2;
                cp16(sA + d, g_xh  + abase[u] + k0 + lch[u] * 8);
                cp16(sB + d, g_w1h + bbase[u] + k0 + lch[u] * 8);
            }
        }
        cp_commit();              // commit every iter (empty group ok)

        __half* As = sh + (kt % 3) * FC1_BUF;
        __half* Bs = As + FC1_ABUF;
        #pragma unroll
        for (int ks = 0; ks < BK; ks += 16) {
            wmma::fragment<wmma::matrix_a, 16, 16, 16, __half, wmma::row_major> af[4];
            wmma::fragment<wmma::matrix_b, 16, 16, 16, __half, wmma::col_major> bf[2];
            #pragma unroll
            for (int i = 0; i < 4; i++)
                wmma::load_matrix_sync(af[i], &As[(wm * 64 + i * 16) * SA + ks], SA);
            #pragma unroll
            for (int j = 0; j < 2; j++)
                wmma::load_matrix_sync(bf[j], &Bs[(wn * 32 + j * 16) * SA + ks], SA);
            #pragma unroll
            for (int i = 0; i < 4; i++)
                #pragma unroll
                for (int j = 0; j < 2; j++)
                    wmma::mma_sync(acc[i][j], af[i], bf[j], acc[i][j]);
        }
    }
    __syncthreads();

    // Epilogue: single pass — full 128x128 C staged COL-MAJOR (ldm=132)
    #pragma unroll
    for (int i = 0; i < 4; i++)
        #pragma unroll
        for (int j = 0; j < 2; j++)
            wmma::store_matrix_sync(&sf[(wn * 32 + j * 16) * PCM + wm * 64 + i * 16],
                                    acc[i][j], PCM, wmma::mem_col_major);
    __syncthreads();
    #pragma unroll
    for (int it = 0; it < 64; it++) {
        int e = tid + it * 256;
        int col = e >> 7, r = e & 127;
        int n = n0 + col;
        g_h0h[(size_t)n * MTOT + m0 + r] =
            __float2half(sf[col * PCM + r] + __ldg(&bias[n]));
    }
}

// ---------------------------------------------------------------------------
// Fused convs (half in/out, fp32 math)
// ---------------------------------------------------------------------------
__global__ __launch_bounds__(256) void conv_fused_kernel(
    const float* __restrict__ w1, const float* __restrict__ b1,
    const float* __restrict__ w2, const float* __restrict__ b2,
    const float* __restrict__ w3, const float* __restrict__ b3,
    const float* __restrict__ wp, const float* __restrict__ pb)
{
    __shared__ float s0[TILE3D];
    __shared__ float s1[TILE3D];

    const int tid = threadIdx.x;
    const int ca  = blockIdx.x % CAv;
    const int b   = blockIdx.x / CAv;
    const size_t base = (size_t)ca * MTOT + (size_t)b * TILE3D;

    for (int i = tid * 4; i < TILE3D; i += 1024) {
        uint2 p = *reinterpret_cast<const uint2*>(&g_h0h[base + i]);
        __half2 h0 = *reinterpret_cast<__half2*>(&p.x);
        __half2 h1 = *reinterpret_cast<__half2*>(&p.y);
        float2 f0 = __half22float2(h0);
        float2 f1 = __half22float2(h1);
        s0[i] = f0.x; s0[i + 1] = f0.y; s0[i + 2] = f1.x; s0[i + 3] = f1.y;
    }

    float wc[27];
    #pragma unroll
    for (int j = 0; j < 27; j++) wc[j] = w3[ca * 27 + j];
    #pragma unroll
    for (int j = 0; j < 9; j++)  wc[9 + j] += w2[ca * 9 + j];
    #pragma unroll
    for (int dt = 0; dt < 3; dt++) wc[dt * 9 + 4] += w1[ca * 3 + dt];
    const float bias3 = (b1[ca] + b2[ca] + b3[ca]) * (1.0f / 3.0f);
    const float wp0 = wp[ca * 3], wp1 = wp[ca * 3 + 1], wp2 = wp[ca * 3 + 2];
    const float pbias = pb[ca];

    __syncthreads();

    for (int e = tid; e < TILE3D; e += 256) {
        int t   = e / NP;
        int pos = e - t * NP;
        int y   = pos / Wv;
        int x   = pos - y * Wv;
        float acc = 0.0f;
        #pragma unroll
        for (int dt = -1; dt <= 1; dt++) {
            int tt = t + dt;
            if ((unsigned)tt >= (unsigned)Tv) continue;
            #pragma unroll
            for (int dy = -1; dy <= 1; dy++) {
                int yy = y + dy;
                if ((unsigned)yy >= (unsigned)Hv) continue;
                #pragma unroll
                for (int dx = -1; dx <= 1; dx++) {
                    int xx = x + dx;
                    if ((unsigned)xx >= (unsigned)Wv) continue;
                    acc += wc[(dt + 1) * 9 + (dy + 1) * 3 + (dx + 1)]
                           * s0[tt * NP + yy * Wv + xx];
                }
            }
        }
        s1[e] = acc * (1.0f / 3.0f) + bias3 + s0[e];
    }
    __syncthreads();

    for (int e = tid; e < TILE3D; e += 256) {
        int t = e / NP;
        float acc = pbias;
        if (t > 0)      acc += wp0 * s1[e - NP];
        acc += wp1 * s1[e];
        if (t < Tv - 1) acc += wp2 * s1[e + NP];
        g_h2h[base + e] = __float2half(s1[e] + acc);
    }
}

// ---------------------------------------------------------------------------
// fc2: out[m, n] = x[m, n] + sum_k h2[k, m] * w[n, k] + bias[n]
// ---------------------------------------------------------------------------
__global__ __launch_bounds__(256, 2) void fc2_kernel(
    const float* __restrict__ bias,
    const float* __restrict__ x,
    float* __restrict__ out)
{
    extern __shared__ __align__(16) unsigned char smem_raw[];
    __half* sh = reinterpret_cast<__half*>(smem_raw);
    float*  sf = reinterpret_cast<float*>(smem_raw);

    const int m0  = blockIdx.y * 128;
    const int n0  = blockIdx.x * 128;
    const int tid = threadIdx.x;
    const int wid = tid >> 5;
    const int wm  = wid & 1;
    const int wn  = wid >> 1;

    wmma::fragment<wmma::accumulator, 16, 16, 16, float> acc[4][2];
    #pragma unroll
    for (int i = 0; i < 4; i++)
        #pragma unroll
        for (int j = 0; j < 2; j++)
            wmma::fill_fragment(acc[i][j], 0.0f);

    int akr[4], amc[4], brow[4], bch[4];
    size_t bbase[4];
    #pragma unroll
    for (int u = 0; u < 4; u++) {
        int idx = tid + u * 256;
        akr[u] = idx >> 4;
        amc[u] = idx & 15;
        brow[u] = idx >> 3;
        bch[u]  = idx & 7;
        bbase[u] = (size_t)(n0 + brow[u]) * CAv;
    }

    constexpr int KT = CAv / BK;   // 6

    #pragma unroll
    for (int p = 0; p < 2; p++) {
        __half* st = sh + p * FC2_BUF;
        uint32_t sA = smem_u32(st);
        uint32_t sB = smem_u32(st + FC2_ABUF);
        int k0 = p * BK;
        #pragma unroll
        for (int u = 0; u < 4; u++) {
            cp16(sA + (uint32_t)(akr[u] * SAT + amc[u] * 8) * 2,
                 g_h2h + (size_t)(k0 + akr[u]) * MTOT + m0 + amc[u] * 8);
            cp16(sB + (uint32_t)(brow[u] * SA + bch[u] * 8) * 2,
                 g_w2h + bbase[u] + k0 + bch[u] * 8);
        }
        cp_commit();
    }

    for (int kt = 0; kt < KT; kt++) {
        cp_wait1();
        __syncthreads();

        if (kt + 2 < KT) {
            int k0 = (kt + 2) * BK;
            __half* st = sh + ((kt + 2) % 3) * FC2_BUF;
            uint32_t sA = smem_u32(st);
            uint32_t sB = smem_u32(st + FC2_ABUF);
            #pragma unroll
            for (int u = 0; u < 4; u++) {
                cp16(sA + (uint32_t)(akr[u] * SAT + amc[u] * 8) * 2,
                     g_h2h + (size_t)(k0 + akr[u]) * MTOT + m0 + amc[u] * 8);
                cp16(sB + (uint32_t)(brow[u] * SA + bch[u] * 8) * 2,
                     g_w2h + bbase[u] + k0 + bch[u] * 8);
            }
        }
        cp_commit();

        __half* As = sh + (kt % 3) * FC2_BUF;
        __half* Bs = As + FC2_ABUF;
        #pragma unroll
        for (int ks = 0; ks < BK; ks += 16) {
            wmma::fragment<wmma::matrix_a, 16, 16, 16, __half, wmma::col_major> af[4];
            wmma::fragment<wmma::matrix_b, 16, 16, 16, __half, wmma::col_major> bf[2];
            #pragma unroll
            for (int i = 0; i < 4; i++)
                wmma::load_matrix_sync(af[i], &As[ks * SAT + wm * 64 + i * 16], SAT);
            #pragma unroll
            for (int j = 0; j < 2; j++)
                wmma::load_matrix_sync(bf[j], &Bs[(wn * 32 + j * 16) * SA + ks], SA);
            #pragma unroll
            for (int i = 0; i < 4; i++)
                #pragma unroll
                for (int j = 0; j < 2; j++)
                    wmma::mma_sync(acc[i][j], af[i], bf[j], acc[i][j]);
        }
    }
    __syncthreads();

    // Epilogue: single pass — full 128x128 C staged ROW-MAJOR (ldm=132)
    #pragma unroll
    for (int i = 0; i < 4; i++)
        #pragma unroll
        for (int j = 0; j < 2; j++)
            wmma::store_matrix_sync(&sf[(wm * 64 + i * 16) * PCM + wn * 32 + j * 16],
                                    acc[i][j], PCM, wmma::mem_row_major);
    __syncthreads();
    #pragma unroll
    for (int it = 0; it < 64; it++) {
        int e = tid + it * 256;
        int c = e & 127, r = e >> 7;
        int m = m0 + r;
        int bt = m / NP;
        int pos = m - bt * NP;
        int n = n0 + c;
        size_t off = ((size_t)(bt * Lv + 1 + pos)) * INC + n;
        out[off] = x[off] + sf[r * PCM + c] + __ldg(&bias[n]);
    }
}

// ---------------------------------------------------------------------------
__global__ __launch_bounds__(256) void cls_kernel(
    const float* __restrict__ x, float* __restrict__ out)
{
    int i = blockIdx.x * 256 + threadIdx.x;
    if (i >= BTv * INC) return;
    int bt = i / INC, c = i % INC;
    size_t off = (size_t)bt * Lv * INC + c;
    out[off] = x[off];
}

// ---------------------------------------------------------------------------
extern "C" void kernel_launch(void* const* d_in, const int* in_sizes, int n_in,
                              void* d_out, int out_size)
{
    const float* x     = (const float*)d_in[0];
    const float* fc1_w = (const float*)d_in[1];
    const float* fc1_b = (const float*)d_in[2];
    const float* c1w   = (const float*)d_in[3];
    const float* c1b   = (const float*)d_in[4];
    const float* c2w   = (const float*)d_in[5];
    const float* c2b   = (const float*)d_in[6];
    const float* c3w   = (const float*)d_in[7];
    const float* c3b   = (const float*)d_in[8];
    const float* pw    = (const float*)d_in[9];
    const float* pb    = (const float*)d_in[10];
    const float* fc2_w = (const float*)d_in[11];
    const float* fc2_b = (const float*)d_in[12];
    float* out = (float*)d_out;

    cudaFuncSetAttribute(fc1_kernel, cudaFuncAttributeMaxDynamicSharedMemorySize, FC1_SMEM);
    cudaFuncSetAttribute(fc2_kernel, cudaFuncAttributeMaxDynamicSharedMemorySize, FC2_SMEM);

    int ncvt = NX4 + 2 * NW4;
    cvt_all_kernel<<<(ncvt + 255) / 256, 256>>>(x, fc1_w, fc2_w);

    dim3 g1(CAv / 128, MTOT / 128);   // (3, 196)
    fc1_kernel<<<g1, 256, FC1_SMEM>>>(fc1_b);

    conv_fused_kernel<<<CAv * (BTv / Tv), 256>>>(c1w, c1b, c2w, c2b, c3w, c3b, pw, pb);

    dim3 g2(INC / 128, MTOT / 128);   // (6, 196)
    fc2_kernel<<<g2, 256, FC2_SMEM>>>(fc2_b, x, out);

    cls_kernel<<<(BTv * INC + 255) / 256, 256>>>(x, out);
}